// round 2
// baseline (speedup 1.0000x reference)
#include <cuda_runtime.h>
#include <cuda_bf16.h>

#define FEAT 1024
#define NH   16
#define HD   64
#define BATCH 8
#define SEQ  1024
#define MROWS (BATCH*SEQ)   // 8192

// ---------------- scratch (device globals; no allocation) ----------------
__device__ float g_q[BATCH*NH*SEQ*HD];     // [bh][t][d]
__device__ float g_k[BATCH*NH*SEQ*HD];
__device__ float g_v[BATCH*NH*SEQ*HD];
__device__ float g_att[MROWS*FEAT];        // [b,t,D]

// ---------------- SGEMM: C[M,N] = A[M,K] @ W[N,K]^T + bias ----------------
// EPILOGUE 0: scatter into q/k/v buffers ([3,H,hd] split of N=3072)
// EPILOGUE 1: plain row-major store to out0 (N=1024)
template<int EPILOGUE>
__global__ __launch_bounds__(256)
void sgemm128(const float* __restrict__ A, const float* __restrict__ W,
              const float* __restrict__ bias,
              float* __restrict__ out0, float* __restrict__ out1, float* __restrict__ out2,
              int N, int K)
{
    __shared__ float As[16][132];
    __shared__ float Bs[16][132];

    const int tid = threadIdx.x;
    const int bm = blockIdx.y * 128;
    const int bn = blockIdx.x * 128;
    const int tr = tid / 16;       // 0..15 -> rows tr*8..tr*8+7
    const int tc = tid % 16;       // 0..15 -> cols tc*8..tc*8+7

    const int lrow = tid >> 2;          // 0..63
    const int lk4  = (tid & 3) * 4;     // 0,4,8,12

    const float* Aptr = A + (size_t)(bm + lrow) * K + lk4;
    const float* Wptr = W + (size_t)(bn + lrow) * K + lk4;

    float acc[8][8];
    #pragma unroll
    for (int i = 0; i < 8; i++)
        #pragma unroll
        for (int j = 0; j < 8; j++) acc[i][j] = 0.f;

    for (int k0 = 0; k0 < K; k0 += 16) {
        float4 a0 = *(const float4*)(Aptr + k0);
        float4 a1 = *(const float4*)(Aptr + (size_t)64 * K + k0);
        float4 b0 = *(const float4*)(Wptr + k0);
        float4 b1 = *(const float4*)(Wptr + (size_t)64 * K + k0);
        __syncthreads();
        As[lk4+0][lrow] = a0.x; As[lk4+1][lrow] = a0.y;
        As[lk4+2][lrow] = a0.z; As[lk4+3][lrow] = a0.w;
        As[lk4+0][lrow+64] = a1.x; As[lk4+1][lrow+64] = a1.y;
        As[lk4+2][lrow+64] = a1.z; As[lk4+3][lrow+64] = a1.w;
        Bs[lk4+0][lrow] = b0.x; Bs[lk4+1][lrow] = b0.y;
        Bs[lk4+2][lrow] = b0.z; Bs[lk4+3][lrow] = b0.w;
        Bs[lk4+0][lrow+64] = b1.x; Bs[lk4+1][lrow+64] = b1.y;
        Bs[lk4+2][lrow+64] = b1.z; Bs[lk4+3][lrow+64] = b1.w;
        __syncthreads();
        #pragma unroll
        for (int kk = 0; kk < 16; kk++) {
            float4 af0 = *(const float4*)&As[kk][tr*8];
            float4 af1 = *(const float4*)&As[kk][tr*8+4];
            float4 bf0 = *(const float4*)&Bs[kk][tc*8];
            float4 bf1 = *(const float4*)&Bs[kk][tc*8+4];
            float a[8] = {af0.x, af0.y, af0.z, af0.w, af1.x, af1.y, af1.z, af1.w};
            float b[8] = {bf0.x, bf0.y, bf0.z, bf0.w, bf1.x, bf1.y, bf1.z, bf1.w};
            #pragma unroll
            for (int i = 0; i < 8; i++)
                #pragma unroll
                for (int j = 0; j < 8; j++)
                    acc[i][j] += a[i] * b[j];
        }
    }

    if (EPILOGUE == 0) {
        // n = s*1024 + h*64 + d ; dest[s][(b*NH+h)*SEQ + t][d]
        #pragma unroll
        for (int i = 0; i < 8; i++) {
            int m = bm + tr*8 + i;
            int b = m >> 10, t = m & 1023;
            #pragma unroll
            for (int jj = 0; jj < 8; jj += 4) {
                int n = bn + tc*8 + jj;
                int s = n >> 10;
                int r = n & 1023;
                int h = r >> 6, d = r & 63;
                float* dst = (s == 0 ? out0 : (s == 1 ? out1 : out2))
                           + (size_t)((b*NH + h)*SEQ + t) * HD + d;
                float4 v;
                v.x = acc[i][jj+0] + bias[n+0];
                v.y = acc[i][jj+1] + bias[n+1];
                v.z = acc[i][jj+2] + bias[n+2];
                v.w = acc[i][jj+3] + bias[n+3];
                *(float4*)dst = v;
            }
        }
    } else {
        #pragma unroll
        for (int i = 0; i < 8; i++) {
            int m = bm + tr*8 + i;
            #pragma unroll
            for (int jj = 0; jj < 8; jj += 4) {
                int n = bn + tc*8 + jj;
                float4 v;
                v.x = acc[i][jj+0] + bias[n+0];
                v.y = acc[i][jj+1] + bias[n+1];
                v.z = acc[i][jj+2] + bias[n+2];
                v.w = acc[i][jj+3] + bias[n+3];
                *(float4*)(out0 + (size_t)m * N + n) = v;
            }
        }
    }
}

// ---------------- attention: per (b,h), 16 query rows per block ----------------
// smem: Qs[16][68], KV[64][68], Ss[16][1028]
#define QS_STRIDE 68
#define KV_STRIDE 68
#define SS_STRIDE 1028
#define ATTN_SMEM ((16*QS_STRIDE + 64*KV_STRIDE + 16*SS_STRIDE) * 4)

__global__ __launch_bounds__(256)
void attn_kernel(const float* __restrict__ q, const float* __restrict__ k,
                 const float* __restrict__ v, const unsigned char* __restrict__ pad,
                 const float* __restrict__ scale_p, float* __restrict__ outbuf)
{
    extern __shared__ float sm[];
    float* Qs = sm;                            // 16 x 68
    float* KV = sm + 16*QS_STRIDE;             // 64 x 68
    float* Ss = sm + 16*QS_STRIDE + 64*KV_STRIDE; // 16 x 1028

    const int bh = blockIdx.x;      // 0..127
    const int b  = bh / NH;
    const int h  = bh % NH;
    const int q0 = blockIdx.y * 16;
    const int tid = threadIdx.x;
    const float scale = *scale_p;

    // load Q tile (scaled): 16*64 floats -> 1 float4/thread
    {
        int idx = tid * 4;
        int rr = idx >> 6, dd = idx & 63;
        float4 t4 = *(const float4*)(q + (size_t)(bh*SEQ + q0 + rr) * HD + dd);
        Qs[rr*QS_STRIDE + dd + 0] = t4.x * scale;
        Qs[rr*QS_STRIDE + dd + 1] = t4.y * scale;
        Qs[rr*QS_STRIDE + dd + 2] = t4.z * scale;
        Qs[rr*QS_STRIDE + dd + 3] = t4.w * scale;
    }

    const int nkt  = (q0 + 16 + 63) / 64;     // causal: key tiles needed
    const int kcnt = nkt * 64;

    const int sr = tid & 15;   // score row
    const int jg = tid >> 4;   // key group (4 keys)

    for (int kt = 0; kt < nkt; kt++) {
        int kbase = kt * 64;
        __syncthreads();
        #pragma unroll
        for (int i = 0; i < 4; i++) {
            int lin = i * 1024 + tid * 4;
            int row = lin >> 6, dd = lin & 63;
            float4 t4 = *(const float4*)(k + (size_t)(bh*SEQ + kbase + row) * HD + dd);
            KV[row*KV_STRIDE + dd + 0] = t4.x;
            KV[row*KV_STRIDE + dd + 1] = t4.y;
            KV[row*KV_STRIDE + dd + 2] = t4.z;
            KV[row*KV_STRIDE + dd + 3] = t4.w;
        }
        __syncthreads();

        float accs[4] = {0.f, 0.f, 0.f, 0.f};
        #pragma unroll
        for (int c = 0; c < 16; c++) {
            float4 q4 = *(const float4*)&Qs[sr*QS_STRIDE + c*4];
            #pragma unroll
            for (int jj = 0; jj < 4; jj++) {
                float4 k4 = *(const float4*)&KV[(jg*4+jj)*KV_STRIDE + c*4];
                accs[jj] += q4.x*k4.x + q4.y*k4.y + q4.z*k4.z + q4.w*k4.w;
            }
        }
        int qrow = q0 + sr;
        #pragma unroll
        for (int jj = 0; jj < 4; jj++) {
            int j = kbase + jg*4 + jj;
            float s = accs[jj];
            if (j > qrow || pad[b*SEQ + j]) s = -1e30f;
            Ss[sr*SS_STRIDE + j] = s;
        }
    }
    __syncthreads();

    // softmax: 16 threads per row
    {
        int r2 = tid >> 4, l16 = tid & 15;
        float mx = -1e30f;
        for (int j = l16; j < kcnt; j += 16) mx = fmaxf(mx, Ss[r2*SS_STRIDE + j]);
        #pragma unroll
        for (int off = 1; off < 16; off <<= 1)
            mx = fmaxf(mx, __shfl_xor_sync(0xffffffffu, mx, off));
        float sum = 0.f;
        for (int j = l16; j < kcnt; j += 16) {
            float e = __expf(Ss[r2*SS_STRIDE + j] - mx);
            Ss[r2*SS_STRIDE + j] = e;
            sum += e;
        }
        #pragma unroll
        for (int off = 1; off < 16; off <<= 1)
            sum += __shfl_xor_sync(0xffffffffu, sum, off);
        float inv = 1.f / sum;
        for (int j = l16; j < kcnt; j += 16) Ss[r2*SS_STRIDE + j] *= inv;
    }

    // AV: thread owns (row = tid>>4, 4 out dims)
    const int orow = tid >> 4;
    const int dg   = tid & 15;
    float acco[4] = {0.f, 0.f, 0.f, 0.f};
    for (int kt = 0; kt < nkt; kt++) {
        int kbase = kt * 64;
        __syncthreads();
        #pragma unroll
        for (int i = 0; i < 4; i++) {
            int lin = i * 1024 + tid * 4;
            int row = lin >> 6, dd = lin & 63;
            float4 t4 = *(const float4*)(v + (size_t)(bh*SEQ + kbase + row) * HD + dd);
            KV[row*KV_STRIDE + dd + 0] = t4.x;
            KV[row*KV_STRIDE + dd + 1] = t4.y;
            KV[row*KV_STRIDE + dd + 2] = t4.z;
            KV[row*KV_STRIDE + dd + 3] = t4.w;
        }
        __syncthreads();
        #pragma unroll 8
        for (int j = 0; j < 64; j++) {
            float p = Ss[orow*SS_STRIDE + kbase + j];
            float4 v4 = *(const float4*)&KV[j*KV_STRIDE + dg*4];
            acco[0] += p * v4.x;
            acco[1] += p * v4.y;
            acco[2] += p * v4.z;
            acco[3] += p * v4.w;
        }
    }
    float4 o4 = {acco[0], acco[1], acco[2], acco[3]};
    *(float4*)(outbuf + (size_t)(b*SEQ + q0 + orow) * FEAT + h*HD + dg*4) = o4;
}

// ---------------- launch ----------------
extern "C" void kernel_launch(void* const* d_in, const int* in_sizes, int n_in,
                              void* d_out, int out_size)
{
    const float* x    = (const float*)d_in[0];
    const unsigned char* pad = (const unsigned char*)d_in[1];
    const float* Wqkv = (const float*)d_in[2];
    const float* bqkv = (const float*)d_in[3];
    const float* Wp   = (const float*)d_in[4];
    const float* bp   = (const float*)d_in[5];
    const float* scale = (const float*)d_in[6];
    float* out = (float*)d_out;

    float *qp, *kp, *vp, *ap;
    cudaGetSymbolAddress((void**)&qp, g_q);
    cudaGetSymbolAddress((void**)&kp, g_k);
    cudaGetSymbolAddress((void**)&vp, g_v);
    cudaGetSymbolAddress((void**)&ap, g_att);

    cudaFuncSetAttribute(attn_kernel, cudaFuncAttributeMaxDynamicSharedMemorySize, ATTN_SMEM);

    dim3 g1(3072/128, 8192/128);
    sgemm128<0><<<g1, 256>>>(x, Wqkv, bqkv, qp, kp, vp, 3072, 1024);

    dim3 g2(BATCH*NH, SEQ/16);
    attn_kernel<<<g2, 256, ATTN_SMEM>>>(qp, kp, vp, pad, scale, ap);

    dim3 g3(1024/128, 8192/128);
    sgemm128<1><<<g3, 256>>>(ap, Wp, bp, out, nullptr, nullptr, 1024, 1024);
}

// round 3
// speedup vs baseline: 1.2698x; 1.2698x over previous
#include <cuda_runtime.h>
#include <cuda_bf16.h>

#define FEAT 1024
#define NH   16
#define HD   64
#define BATCH 8
#define SEQ  1024
#define MROWS (BATCH*SEQ)   // 8192

// ---------------- scratch (device globals; no allocation) ----------------
__device__ float g_q[BATCH*NH*SEQ*HD];     // [bh][t][d]
__device__ float g_k[BATCH*NH*SEQ*HD];
__device__ float g_v[BATCH*NH*SEQ*HD];
__device__ float g_att[MROWS*FEAT];        // [b,t,D]

// ---------------- SGEMM: C[M,N] = A[M,K] @ W[N,K]^T + bias ----------------
// double-buffered smem, one sync per k-step.
// EPILOGUE 0: scatter into q/k/v buffers ([3,H,hd] split of N=3072)
// EPILOGUE 1: plain row-major store to out0
template<int EPILOGUE>
__global__ __launch_bounds__(256, 2)
void sgemm128(const float* __restrict__ A, const float* __restrict__ W,
              const float* __restrict__ bias,
              float* __restrict__ out0, float* __restrict__ out1, float* __restrict__ out2,
              int N, int K)
{
    __shared__ float As[2][16][132];
    __shared__ float Bs[2][16][132];

    const int tid = threadIdx.x;
    const int bm = blockIdx.y * 128;
    const int bn = blockIdx.x * 128;
    const int tr = tid / 16;       // 0..15 -> rows tr*8..tr*8+7
    const int tc = tid % 16;       // 0..15 -> cols tc*8..tc*8+7

    const int lrow = tid >> 2;          // 0..63
    const int lk4  = (tid & 3) * 4;     // 0,4,8,12

    const float* Aptr = A + (size_t)(bm + lrow) * K + lk4;
    const float* Wptr = W + (size_t)(bn + lrow) * K + lk4;

    float acc[8][8];
    #pragma unroll
    for (int i = 0; i < 8; i++)
        #pragma unroll
        for (int j = 0; j < 8; j++) acc[i][j] = 0.f;

    // prologue: tile 0 -> buffer 0
    {
        float4 a0 = *(const float4*)(Aptr);
        float4 a1 = *(const float4*)(Aptr + (size_t)64 * K);
        float4 b0 = *(const float4*)(Wptr);
        float4 b1 = *(const float4*)(Wptr + (size_t)64 * K);
        As[0][lk4+0][lrow] = a0.x; As[0][lk4+1][lrow] = a0.y;
        As[0][lk4+2][lrow] = a0.z; As[0][lk4+3][lrow] = a0.w;
        As[0][lk4+0][lrow+64] = a1.x; As[0][lk4+1][lrow+64] = a1.y;
        As[0][lk4+2][lrow+64] = a1.z; As[0][lk4+3][lrow+64] = a1.w;
        Bs[0][lk4+0][lrow] = b0.x; Bs[0][lk4+1][lrow] = b0.y;
        Bs[0][lk4+2][lrow] = b0.z; Bs[0][lk4+3][lrow] = b0.w;
        Bs[0][lk4+0][lrow+64] = b1.x; Bs[0][lk4+1][lrow+64] = b1.y;
        Bs[0][lk4+2][lrow+64] = b1.z; Bs[0][lk4+3][lrow+64] = b1.w;
    }
    __syncthreads();

    int p = 0;
    for (int k0 = 16; k0 <= K; k0 += 16) {
        const bool more = (k0 < K);
        float4 na0, na1, nb0, nb1;
        if (more) {
            na0 = *(const float4*)(Aptr + k0);
            na1 = *(const float4*)(Aptr + (size_t)64 * K + k0);
            nb0 = *(const float4*)(Wptr + k0);
            nb1 = *(const float4*)(Wptr + (size_t)64 * K + k0);
        }
        #pragma unroll
        for (int kk = 0; kk < 16; kk++) {
            float4 af0 = *(const float4*)&As[p][kk][tr*8];
            float4 af1 = *(const float4*)&As[p][kk][tr*8+4];
            float4 bf0 = *(const float4*)&Bs[p][kk][tc*8];
            float4 bf1 = *(const float4*)&Bs[p][kk][tc*8+4];
            float a[8] = {af0.x, af0.y, af0.z, af0.w, af1.x, af1.y, af1.z, af1.w};
            float b[8] = {bf0.x, bf0.y, bf0.z, bf0.w, bf1.x, bf1.y, bf1.z, bf1.w};
            #pragma unroll
            for (int i = 0; i < 8; i++)
                #pragma unroll
                for (int j = 0; j < 8; j++)
                    acc[i][j] += a[i] * b[j];
        }
        if (more) {
            int q = p ^ 1;
            As[q][lk4+0][lrow] = na0.x; As[q][lk4+1][lrow] = na0.y;
            As[q][lk4+2][lrow] = na0.z; As[q][lk4+3][lrow] = na0.w;
            As[q][lk4+0][lrow+64] = na1.x; As[q][lk4+1][lrow+64] = na1.y;
            As[q][lk4+2][lrow+64] = na1.z; As[q][lk4+3][lrow+64] = na1.w;
            Bs[q][lk4+0][lrow] = nb0.x; Bs[q][lk4+1][lrow] = nb0.y;
            Bs[q][lk4+2][lrow] = nb0.z; Bs[q][lk4+3][lrow] = nb0.w;
            Bs[q][lk4+0][lrow+64] = nb1.x; Bs[q][lk4+1][lrow+64] = nb1.y;
            Bs[q][lk4+2][lrow+64] = nb1.z; Bs[q][lk4+3][lrow+64] = nb1.w;
        }
        __syncthreads();
        p ^= 1;
    }

    if (EPILOGUE == 0) {
        #pragma unroll
        for (int i = 0; i < 8; i++) {
            int m = bm + tr*8 + i;
            int b = m >> 10, t = m & 1023;
            #pragma unroll
            for (int jj = 0; jj < 8; jj += 4) {
                int n = bn + tc*8 + jj;
                int s = n >> 10;
                int r = n & 1023;
                int h = r >> 6, d = r & 63;
                float* dst = (s == 0 ? out0 : (s == 1 ? out1 : out2))
                           + (size_t)((b*NH + h)*SEQ + t) * HD + d;
                float4 v;
                v.x = acc[i][jj+0] + bias[n+0];
                v.y = acc[i][jj+1] + bias[n+1];
                v.z = acc[i][jj+2] + bias[n+2];
                v.w = acc[i][jj+3] + bias[n+3];
                *(float4*)dst = v;
            }
        }
    } else {
        #pragma unroll
        for (int i = 0; i < 8; i++) {
            int m = bm + tr*8 + i;
            #pragma unroll
            for (int jj = 0; jj < 8; jj += 4) {
                int n = bn + tc*8 + jj;
                float4 v;
                v.x = acc[i][jj+0] + bias[n+0];
                v.y = acc[i][jj+1] + bias[n+1];
                v.z = acc[i][jj+2] + bias[n+2];
                v.w = acc[i][jj+3] + bias[n+3];
                *(float4*)(out0 + (size_t)m * N + n) = v;
            }
        }
    }
}

// ---------------- flash attention: 64 q-rows/CTA, 64-key tiles ----------------
#define AT_STRIDE 68
#define FA_SMEM (4*64*AT_STRIDE*4 + 1024)

__global__ __launch_bounds__(256)
void flash_attn(const float* __restrict__ q, const float* __restrict__ k,
                const float* __restrict__ v, const unsigned char* __restrict__ pad,
                const float* __restrict__ scale_p, float* __restrict__ outbuf)
{
    extern __shared__ float sm[];
    float* Qt = sm;                       // [d][r]  64x68
    float* Kt = Qt + 64*AT_STRIDE;        // [d][c]  64x68
    float* Vs = Kt + 64*AT_STRIDE;        // [c][d]  64x68
    float* Ps = Vs + 64*AT_STRIDE;        // [r][c]  64x68
    unsigned char* spad = (unsigned char*)(Ps + 64*AT_STRIDE);  // [1024]

    const int bh = blockIdx.x;            // 0..127
    const int b  = bh >> 4;
    const int h  = bh & 15;
    const int qb = (gridDim.y - 1) - blockIdx.y;   // heavy blocks first
    const int q0 = qb * 64;
    const int tid = threadIdx.x;
    const int rg = tid >> 4;              // row group 0..15
    const int kg = tid & 15;              // key/dim group 0..15
    const float scale = *scale_p;

    // pad row -> smem (1024 bytes)
    ((int*)spad)[tid] = ((const int*)(pad + (size_t)b*SEQ))[tid];

    // Q tile, transposed + scaled
    {
        const float* qbase = q + ((size_t)bh*SEQ + q0) * HD;
        int row = tid & 63;
        int dbase = (tid >> 6) * 16;
        #pragma unroll
        for (int r = 0; r < 4; r++) {
            int d0 = dbase + r*4;
            float4 t4 = *(const float4*)(qbase + (size_t)row*HD + d0);
            Qt[(d0+0)*AT_STRIDE + row] = t4.x * scale;
            Qt[(d0+1)*AT_STRIDE + row] = t4.y * scale;
            Qt[(d0+2)*AT_STRIDE + row] = t4.z * scale;
            Qt[(d0+3)*AT_STRIDE + row] = t4.w * scale;
        }
    }

    float m_i[4], l_i[4], o[4][4];
    #pragma unroll
    for (int i = 0; i < 4; i++) {
        m_i[i] = -1e30f; l_i[i] = 0.f;
        #pragma unroll
        for (int j = 0; j < 4; j++) o[i][j] = 0.f;
    }

    const int nkt = qb + 1;
    const float* kbp = k + (size_t)bh*SEQ*HD;
    const float* vbp = v + (size_t)bh*SEQ*HD;

    for (int kt = 0; kt < nkt; kt++) {
        const int kb = kt * 64;
        const bool diag = (kt == nkt - 1);
        __syncthreads();
        // K tile transposed
        {
            int row = tid & 63;
            int dbase = (tid >> 6) * 16;
            #pragma unroll
            for (int r = 0; r < 4; r++) {
                int d0 = dbase + r*4;
                float4 t4 = *(const float4*)(kbp + (size_t)(kb + row)*HD + d0);
                Kt[(d0+0)*AT_STRIDE + row] = t4.x;
                Kt[(d0+1)*AT_STRIDE + row] = t4.y;
                Kt[(d0+2)*AT_STRIDE + row] = t4.z;
                Kt[(d0+3)*AT_STRIDE + row] = t4.w;
            }
        }
        // V tile natural layout
        #pragma unroll
        for (int r = 0; r < 4; r++) {
            int lin = r * 1024 + tid * 4;
            int row = lin >> 6, dd = lin & 63;
            float4 t4 = *(const float4*)(vbp + (size_t)(kb + row)*HD + dd);
            *(float4*)&Vs[row*AT_STRIDE + dd] = t4;
        }
        __syncthreads();

        // S = Q K^T  (4x4 microtile per thread)
        float s[4][4];
        #pragma unroll
        for (int i = 0; i < 4; i++)
            #pragma unroll
            for (int j = 0; j < 4; j++) s[i][j] = 0.f;
        #pragma unroll 8
        for (int d = 0; d < 64; d++) {
            float4 qv = *(const float4*)&Qt[d*AT_STRIDE + rg*4];
            float4 kv = *(const float4*)&Kt[d*AT_STRIDE + kg*4];
            float qa[4] = {qv.x, qv.y, qv.z, qv.w};
            float ka[4] = {kv.x, kv.y, kv.z, kv.w};
            #pragma unroll
            for (int i = 0; i < 4; i++)
                #pragma unroll
                for (int j = 0; j < 4; j++)
                    s[i][j] += qa[i] * ka[j];
        }

        // mask: padding always; causal only on the diagonal tile
        if (diag) {
            #pragma unroll
            for (int j = 0; j < 4; j++) {
                int col = kb + kg*4 + j;
                bool pd = spad[col] != 0;
                #pragma unroll
                for (int i = 0; i < 4; i++)
                    if (pd || col > q0 + rg*4 + i) s[i][j] = -1e30f;
            }
        } else {
            #pragma unroll
            for (int j = 0; j < 4; j++) {
                if (spad[kb + kg*4 + j]) {
                    #pragma unroll
                    for (int i = 0; i < 4; i++) s[i][j] = -1e30f;
                }
            }
        }

        // online softmax update per row (16 lanes share a row group)
        #pragma unroll
        for (int i = 0; i < 4; i++) {
            float tm = fmaxf(fmaxf(s[i][0], s[i][1]), fmaxf(s[i][2], s[i][3]));
            #pragma unroll
            for (int off = 1; off < 16; off <<= 1)
                tm = fmaxf(tm, __shfl_xor_sync(0xffffffffu, tm, off));
            float mnew = fmaxf(m_i[i], tm);
            float corr = __expf(m_i[i] - mnew);
            m_i[i] = mnew;
            float p0 = __expf(s[i][0] - mnew);
            float p1 = __expf(s[i][1] - mnew);
            float p2 = __expf(s[i][2] - mnew);
            float p3 = __expf(s[i][3] - mnew);
            float rs = (p0 + p1) + (p2 + p3);
            #pragma unroll
            for (int off = 1; off < 16; off <<= 1)
                rs += __shfl_xor_sync(0xffffffffu, rs, off);
            l_i[i] = l_i[i] * corr + rs;
            #pragma unroll
            for (int j = 0; j < 4; j++) o[i][j] *= corr;
            *(float4*)&Ps[(rg*4 + i)*AT_STRIDE + kg*4] = make_float4(p0, p1, p2, p3);
        }
        __syncthreads();

        // O += P V   (P read as broadcast scalars, V as float4)
        #pragma unroll 4
        for (int c = 0; c < 64; c++) {
            float4 vv = *(const float4*)&Vs[c*AT_STRIDE + kg*4];
            float pr0 = Ps[(rg*4 + 0)*AT_STRIDE + c];
            float pr1 = Ps[(rg*4 + 1)*AT_STRIDE + c];
            float pr2 = Ps[(rg*4 + 2)*AT_STRIDE + c];
            float pr3 = Ps[(rg*4 + 3)*AT_STRIDE + c];
            o[0][0] += pr0*vv.x; o[0][1] += pr0*vv.y; o[0][2] += pr0*vv.z; o[0][3] += pr0*vv.w;
            o[1][0] += pr1*vv.x; o[1][1] += pr1*vv.y; o[1][2] += pr1*vv.z; o[1][3] += pr1*vv.w;
            o[2][0] += pr2*vv.x; o[2][1] += pr2*vv.y; o[2][2] += pr2*vv.z; o[2][3] += pr2*vv.w;
            o[3][0] += pr3*vv.x; o[3][1] += pr3*vv.y; o[3][2] += pr3*vv.z; o[3][3] += pr3*vv.w;
        }
    }

    // normalize and store: [b, q0+row, h*64 + d]
    #pragma unroll
    for (int i = 0; i < 4; i++) {
        float inv = 1.f / l_i[i];
        float4 o4 = {o[i][0]*inv, o[i][1]*inv, o[i][2]*inv, o[i][3]*inv};
        *(float4*)(outbuf + (size_t)(b*SEQ + q0 + rg*4 + i)*FEAT + h*HD + kg*4) = o4;
    }
}

// ---------------- launch ----------------
extern "C" void kernel_launch(void* const* d_in, const int* in_sizes, int n_in,
                              void* d_out, int out_size)
{
    const float* x    = (const float*)d_in[0];
    const unsigned char* pad = (const unsigned char*)d_in[1];
    const float* Wqkv = (const float*)d_in[2];
    const float* bqkv = (const float*)d_in[3];
    const float* Wp   = (const float*)d_in[4];
    const float* bp   = (const float*)d_in[5];
    const float* scale = (const float*)d_in[6];
    float* out = (float*)d_out;

    float *qp, *kp, *vp, *ap;
    cudaGetSymbolAddress((void**)&qp, g_q);
    cudaGetSymbolAddress((void**)&kp, g_k);
    cudaGetSymbolAddress((void**)&vp, g_v);
    cudaGetSymbolAddress((void**)&ap, g_att);

    cudaFuncSetAttribute(flash_attn, cudaFuncAttributeMaxDynamicSharedMemorySize, FA_SMEM);

    dim3 g1(3072/128, 8192/128);
    sgemm128<0><<<g1, 256>>>(x, Wqkv, bqkv, qp, kp, vp, 3072, 1024);

    dim3 g2(BATCH*NH, SEQ/64);
    flash_attn<<<g2, 256, FA_SMEM>>>(qp, kp, vp, pad, scale, ap);

    dim3 g3(1024/128, 8192/128);
    sgemm128<1><<<g3, 256>>>(ap, Wp, bp, out, nullptr, nullptr, 1024, 1024);
}

// round 4
// speedup vs baseline: 2.3866x; 1.8795x over previous
#include <cuda_runtime.h>
#include <cuda_bf16.h>

#define FEAT 1024
#define NH   16
#define HD   64
#define BATCH 8
#define SEQ  1024

// ---------------- scratch (device globals; no allocation) ----------------
__device__ __nv_bfloat16 g_xh[8192*1024],  g_xl[8192*1024];
__device__ __nv_bfloat16 g_wqh[3072*1024], g_wql[3072*1024];
__device__ __nv_bfloat16 g_wph[1024*1024], g_wpl[1024*1024];
__device__ __nv_bfloat16 g_ah[8192*1024],  g_al[8192*1024];
__device__ float g_q[BATCH*NH*SEQ*HD];
__device__ float g_k[BATCH*NH*SEQ*HD];
__device__ float g_v[BATCH*NH*SEQ*HD];

// ---------------- fp32 -> bf16 hi/lo split ----------------
__global__ __launch_bounds__(256)
void split_fp32(const float* __restrict__ src, __nv_bfloat16* __restrict__ hi,
                __nv_bfloat16* __restrict__ lo, int n4)
{
    int i = blockIdx.x * blockDim.x + threadIdx.x;
    if (i >= n4) return;
    float4 v = ((const float4*)src)[i];
    __nv_bfloat16 h0 = __float2bfloat16(v.x);
    __nv_bfloat16 h1 = __float2bfloat16(v.y);
    __nv_bfloat16 h2 = __float2bfloat16(v.z);
    __nv_bfloat16 h3 = __float2bfloat16(v.w);
    __nv_bfloat162 hp0; hp0.x = h0; hp0.y = h1;
    __nv_bfloat162 hp1; hp1.x = h2; hp1.y = h3;
    ((__nv_bfloat162*)hi)[2*i+0] = hp0;
    ((__nv_bfloat162*)hi)[2*i+1] = hp1;
    __nv_bfloat162 lp0, lp1;
    lp0.x = __float2bfloat16(v.x - __bfloat162float(h0));
    lp0.y = __float2bfloat16(v.y - __bfloat162float(h1));
    lp1.x = __float2bfloat16(v.z - __bfloat162float(h2));
    lp1.y = __float2bfloat16(v.w - __bfloat162float(h3));
    ((__nv_bfloat162*)lo)[2*i+0] = lp0;
    ((__nv_bfloat162*)lo)[2*i+1] = lp1;
}

// ---------------- tensor-core GEMM: C = A @ W^T + bias (bf16x3) ----------------
__device__ __forceinline__ void ldsm4(unsigned r[4], unsigned addr) {
    asm volatile("ldmatrix.sync.aligned.m8n8.x4.shared.b16 {%0,%1,%2,%3}, [%4];\n"
                 : "=r"(r[0]), "=r"(r[1]), "=r"(r[2]), "=r"(r[3]) : "r"(addr));
}
__device__ __forceinline__ void mma_bf16(float c[4], const unsigned a[4], const unsigned b[2]) {
    asm volatile("mma.sync.aligned.m16n8k16.row.col.f32.bf16.bf16.f32 "
                 "{%0,%1,%2,%3}, {%4,%5,%6,%7}, {%8,%9}, {%0,%1,%2,%3};\n"
                 : "+f"(c[0]), "+f"(c[1]), "+f"(c[2]), "+f"(c[3])
                 : "r"(a[0]), "r"(a[1]), "r"(a[2]), "r"(a[3]), "r"(b[0]), "r"(b[1]));
}
__device__ __forceinline__ void cp16(unsigned dst, const void* src) {
    asm volatile("cp.async.cg.shared.global [%0], [%1], 16;\n" :: "r"(dst), "l"(src));
}

#define AST 40                   // bf16 elems per smem row (32 + 8 pad)
#define PLANE_B (128*AST*2)      // 10240 bytes per plane
#define BUF_B (4*PLANE_B)        // Ah, Al, Wh, Wl
#define GEMM_SMEM (2*BUF_B)      // 81920 double-buffered

// EPILOGUE 0: scatter to q/k/v ; EPILOGUE 1: row-major to out0
template<int EPILOGUE>
__global__ __launch_bounds__(256)
void gemm_bf3(const __nv_bfloat16* __restrict__ Ah, const __nv_bfloat16* __restrict__ Al,
              const __nv_bfloat16* __restrict__ Wh, const __nv_bfloat16* __restrict__ Wl,
              const float* __restrict__ bias,
              float* __restrict__ out0, float* __restrict__ out1, float* __restrict__ out2,
              int N, int K)
{
    extern __shared__ __nv_bfloat16 sm[];
    const int tid = threadIdx.x;
    const int bm = blockIdx.y * 128, bn = blockIdx.x * 128;
    const int w = tid >> 5, l = tid & 31;
    const int wm = w >> 2, wn = w & 3;

    const int lrow = tid >> 1, lcol = (tid & 1) * 16;
    const __nv_bfloat16* gA0 = Ah + (size_t)(bm + lrow) * K + lcol;
    const __nv_bfloat16* gA1 = Al + (size_t)(bm + lrow) * K + lcol;
    const __nv_bfloat16* gB0 = Wh + (size_t)(bn + lrow) * K + lcol;
    const __nv_bfloat16* gB1 = Wl + (size_t)(bn + lrow) * K + lcol;

    const unsigned sbase = (unsigned)__cvta_generic_to_shared(sm);
    const unsigned sst = sbase + lrow * (AST*2) + lcol * 2;

    float acc[4][4][4];
    #pragma unroll
    for (int i = 0; i < 4; i++)
        #pragma unroll
        for (int j = 0; j < 4; j++)
            #pragma unroll
            for (int r = 0; r < 4; r++) acc[i][j][r] = 0.f;

    // --- tile loader (cp.async) ---
    auto issue = [&](int k0, int buf) {
        unsigned d = sst + buf * BUF_B;
        cp16(d,              gA0 + k0); cp16(d + 16,              gA0 + k0 + 8);
        cp16(d +   PLANE_B,  gA1 + k0); cp16(d +   PLANE_B + 16,  gA1 + k0 + 8);
        cp16(d + 2*PLANE_B,  gB0 + k0); cp16(d + 2*PLANE_B + 16,  gB0 + k0 + 8);
        cp16(d + 3*PLANE_B,  gB1 + k0); cp16(d + 3*PLANE_B + 16,  gB1 + k0 + 8);
        asm volatile("cp.async.commit_group;\n" ::: "memory");
    };

    issue(0, 0);
    int buf = 0;
    for (int k0 = 0; k0 < K; k0 += 32) {
        const bool more = (k0 + 32) < K;
        if (more) {
            issue(k0 + 32, buf ^ 1);
            asm volatile("cp.async.wait_group 1;\n" ::: "memory");
        } else {
            asm volatile("cp.async.wait_group 0;\n" ::: "memory");
        }
        __syncthreads();

        unsigned base = sbase + buf * BUF_B;
        #pragma unroll
        for (int g = 0; g < 2; g++) {
            unsigned ah[4][4], al[4][4], bh[4][2], bl[4][2];
            const int acol = g * 16 + (l >> 4) * 8;
            #pragma unroll
            for (int mt = 0; mt < 4; mt++) {
                int row = wm * 64 + mt * 16 + (l & 15);
                unsigned ad = base + row * (AST*2) + acol * 2;
                ldsm4(ah[mt], ad);
                ldsm4(al[mt], ad + PLANE_B);
            }
            {
                const int quad = l >> 3;
                const int nsub = quad >> 1, khalf = quad & 1;
                #pragma unroll
                for (int p = 0; p < 2; p++) {
                    int row = wn * 32 + (p*2 + nsub) * 8 + (l & 7);
                    int col = g * 16 + khalf * 8;
                    unsigned bd = base + 2*PLANE_B + row * (AST*2) + col * 2;
                    unsigned t[4];
                    ldsm4(t, bd);
                    bh[p*2][0] = t[0]; bh[p*2][1] = t[1];
                    bh[p*2+1][0] = t[2]; bh[p*2+1][1] = t[3];
                    ldsm4(t, bd + PLANE_B);
                    bl[p*2][0] = t[0]; bl[p*2][1] = t[1];
                    bl[p*2+1][0] = t[2]; bl[p*2+1][1] = t[3];
                }
            }
            #pragma unroll
            for (int mt = 0; mt < 4; mt++)
                #pragma unroll
                for (int nt = 0; nt < 4; nt++)
                    mma_bf16(acc[mt][nt], ah[mt], bh[nt]);
            #pragma unroll
            for (int mt = 0; mt < 4; mt++)
                #pragma unroll
                for (int nt = 0; nt < 4; nt++)
                    mma_bf16(acc[mt][nt], ah[mt], bl[nt]);
            #pragma unroll
            for (int mt = 0; mt < 4; mt++)
                #pragma unroll
                for (int nt = 0; nt < 4; nt++)
                    mma_bf16(acc[mt][nt], al[mt], bh[nt]);
        }
        __syncthreads();
        buf ^= 1;
    }

    // --- epilogue ---
    const int gid = l >> 2, qid = l & 3;
    #pragma unroll
    for (int mt = 0; mt < 4; mt++) {
        #pragma unroll
        for (int nt = 0; nt < 4; nt++) {
            int n0 = bn + wn * 32 + nt * 8 + qid * 2;
            float bx = bias[n0], by = bias[n0 + 1];
            #pragma unroll
            for (int half = 0; half < 2; half++) {
                int m = bm + wm * 64 + mt * 16 + gid + half * 8;
                float cx = acc[mt][nt][half*2 + 0] + bx;
                float cy = acc[mt][nt][half*2 + 1] + by;
                float2 v2 = {cx, cy};
                if (EPILOGUE == 0) {
                    int b = m >> 10, t = m & 1023;
                    int s = n0 >> 10, r = n0 & 1023;
                    int hh = r >> 6, d = r & 63;
                    float* dst = (s == 0 ? out0 : (s == 1 ? out1 : out2))
                               + (size_t)((b*NH + hh)*SEQ + t) * HD + d;
                    *(float2*)dst = v2;
                } else {
                    *(float2*)(out0 + (size_t)m * N + n0) = v2;
                }
            }
        }
    }
}

// ---------------- flash attention: 64 q-rows/CTA, 64-key tiles ----------------
#define AT_STRIDE 68
#define FA_SMEM (4*64*AT_STRIDE*4 + 1024)

__global__ __launch_bounds__(256)
void flash_attn(const float* __restrict__ q, const float* __restrict__ k,
                const float* __restrict__ v, const unsigned char* __restrict__ pad,
                const float* __restrict__ scale_p,
                __nv_bfloat16* __restrict__ outh, __nv_bfloat16* __restrict__ outl)
{
    extern __shared__ float smf[];
    float* Qt = smf;                      // [d][r]  64x68
    float* Kt = Qt + 64*AT_STRIDE;        // [d][c]
    float* Vs = Kt + 64*AT_STRIDE;        // [c][d]
    float* Ps = Vs + 64*AT_STRIDE;        // [r][c]
    unsigned char* spad = (unsigned char*)(Ps + 64*AT_STRIDE);  // [1024]

    const int bh = blockIdx.x;
    const int b  = bh >> 4;
    const int h  = bh & 15;
    const int qb = (gridDim.y - 1) - blockIdx.y;
    const int q0 = qb * 64;
    const int tid = threadIdx.x;
    const int rg = tid >> 4;
    const int kg = tid & 15;
    const float scale = *scale_p;

    ((int*)spad)[tid] = ((const int*)(pad + (size_t)b*SEQ))[tid];

    {
        const float* qbase = q + ((size_t)bh*SEQ + q0) * HD;
        int row = tid & 63;
        int dbase = (tid >> 6) * 16;
        #pragma unroll
        for (int r = 0; r < 4; r++) {
            int d0 = dbase + r*4;
            float4 t4 = *(const float4*)(qbase + (size_t)row*HD + d0);
            Qt[(d0+0)*AT_STRIDE + row] = t4.x * scale;
            Qt[(d0+1)*AT_STRIDE + row] = t4.y * scale;
            Qt[(d0+2)*AT_STRIDE + row] = t4.z * scale;
            Qt[(d0+3)*AT_STRIDE + row] = t4.w * scale;
        }
    }

    float m_i[4], l_i[4], o[4][4];
    #pragma unroll
    for (int i = 0; i < 4; i++) {
        m_i[i] = -1e30f; l_i[i] = 0.f;
        #pragma unroll
        for (int j = 0; j < 4; j++) o[i][j] = 0.f;
    }

    const int nkt = qb + 1;
    const float* kbp = k + (size_t)bh*SEQ*HD;
    const float* vbp = v + (size_t)bh*SEQ*HD;

    for (int kt = 0; kt < nkt; kt++) {
        const int kb = kt * 64;
        const bool diag = (kt == nkt - 1);
        __syncthreads();
        {
            int row = tid & 63;
            int dbase = (tid >> 6) * 16;
            #pragma unroll
            for (int r = 0; r < 4; r++) {
                int d0 = dbase + r*4;
                float4 t4 = *(const float4*)(kbp + (size_t)(kb + row)*HD + d0);
                Kt[(d0+0)*AT_STRIDE + row] = t4.x;
                Kt[(d0+1)*AT_STRIDE + row] = t4.y;
                Kt[(d0+2)*AT_STRIDE + row] = t4.z;
                Kt[(d0+3)*AT_STRIDE + row] = t4.w;
            }
        }
        #pragma unroll
        for (int r = 0; r < 4; r++) {
            int lin = r * 1024 + tid * 4;
            int row = lin >> 6, dd = lin & 63;
            float4 t4 = *(const float4*)(vbp + (size_t)(kb + row)*HD + dd);
            *(float4*)&Vs[row*AT_STRIDE + dd] = t4;
        }
        __syncthreads();

        float s[4][4];
        #pragma unroll
        for (int i = 0; i < 4; i++)
            #pragma unroll
            for (int j = 0; j < 4; j++) s[i][j] = 0.f;
        #pragma unroll 8
        for (int d = 0; d < 64; d++) {
            float4 qv = *(const float4*)&Qt[d*AT_STRIDE + rg*4];
            float4 kv = *(const float4*)&Kt[d*AT_STRIDE + kg*4];
            float qa[4] = {qv.x, qv.y, qv.z, qv.w};
            float ka[4] = {kv.x, kv.y, kv.z, kv.w};
            #pragma unroll
            for (int i = 0; i < 4; i++)
                #pragma unroll
                for (int j = 0; j < 4; j++)
                    s[i][j] += qa[i] * ka[j];
        }

        if (diag) {
            #pragma unroll
            for (int j = 0; j < 4; j++) {
                int col = kb + kg*4 + j;
                bool pd = spad[col] != 0;
                #pragma unroll
                for (int i = 0; i < 4; i++)
                    if (pd || col > q0 + rg*4 + i) s[i][j] = -1e30f;
            }
        } else {
            #pragma unroll
            for (int j = 0; j < 4; j++) {
                if (spad[kb + kg*4 + j]) {
                    #pragma unroll
                    for (int i = 0; i < 4; i++) s[i][j] = -1e30f;
                }
            }
        }

        #pragma unroll
        for (int i = 0; i < 4; i++) {
            float tm = fmaxf(fmaxf(s[i][0], s[i][1]), fmaxf(s[i][2], s[i][3]));
            #pragma unroll
            for (int off = 1; off < 16; off <<= 1)
                tm = fmaxf(tm, __shfl_xor_sync(0xffffffffu, tm, off));
            float mnew = fmaxf(m_i[i], tm);
            float corr = __expf(m_i[i] - mnew);
            m_i[i] = mnew;
            float p0 = __expf(s[i][0] - mnew);
            float p1 = __expf(s[i][1] - mnew);
            float p2 = __expf(s[i][2] - mnew);
            float p3 = __expf(s[i][3] - mnew);
            float rs = (p0 + p1) + (p2 + p3);
            #pragma unroll
            for (int off = 1; off < 16; off <<= 1)
                rs += __shfl_xor_sync(0xffffffffu, rs, off);
            l_i[i] = l_i[i] * corr + rs;
            #pragma unroll
            for (int j = 0; j < 4; j++) o[i][j] *= corr;
            *(float4*)&Ps[(rg*4 + i)*AT_STRIDE + kg*4] = make_float4(p0, p1, p2, p3);
        }
        __syncthreads();

        #pragma unroll 4
        for (int c = 0; c < 64; c++) {
            float4 vv = *(const float4*)&Vs[c*AT_STRIDE + kg*4];
            float pr0 = Ps[(rg*4 + 0)*AT_STRIDE + c];
            float pr1 = Ps[(rg*4 + 1)*AT_STRIDE + c];
            float pr2 = Ps[(rg*4 + 2)*AT_STRIDE + c];
            float pr3 = Ps[(rg*4 + 3)*AT_STRIDE + c];
            o[0][0] += pr0*vv.x; o[0][1] += pr0*vv.y; o[0][2] += pr0*vv.z; o[0][3] += pr0*vv.w;
            o[1][0] += pr1*vv.x; o[1][1] += pr1*vv.y; o[1][2] += pr1*vv.z; o[1][3] += pr1*vv.w;
            o[2][0] += pr2*vv.x; o[2][1] += pr2*vv.y; o[2][2] += pr2*vv.z; o[2][3] += pr2*vv.w;
            o[3][0] += pr3*vv.x; o[3][1] += pr3*vv.y; o[3][2] += pr3*vv.z; o[3][3] += pr3*vv.w;
        }
    }

    // normalize, split to bf16 hi/lo, store to [b, t, h*64+d]
    #pragma unroll
    for (int i = 0; i < 4; i++) {
        float inv = 1.f / l_i[i];
        float o0 = o[i][0]*inv, o1 = o[i][1]*inv, o2 = o[i][2]*inv, o3 = o[i][3]*inv;
        size_t off = (size_t)(b*SEQ + q0 + rg*4 + i)*FEAT + h*HD + kg*4;
        __nv_bfloat16 b0 = __float2bfloat16(o0);
        __nv_bfloat16 b1 = __float2bfloat16(o1);
        __nv_bfloat16 b2 = __float2bfloat16(o2);
        __nv_bfloat16 b3 = __float2bfloat16(o3);
        __nv_bfloat162 hp0; hp0.x = b0; hp0.y = b1;
        __nv_bfloat162 hp1; hp1.x = b2; hp1.y = b3;
        *(__nv_bfloat162*)(outh + off)     = hp0;
        *(__nv_bfloat162*)(outh + off + 2) = hp1;
        __nv_bfloat162 lp0, lp1;
        lp0.x = __float2bfloat16(o0 - __bfloat162float(b0));
        lp0.y = __float2bfloat16(o1 - __bfloat162float(b1));
        lp1.x = __float2bfloat16(o2 - __bfloat162float(b2));
        lp1.y = __float2bfloat16(o3 - __bfloat162float(b3));
        *(__nv_bfloat162*)(outl + off)     = lp0;
        *(__nv_bfloat162*)(outl + off + 2) = lp1;
    }
}

// ---------------- launch ----------------
extern "C" void kernel_launch(void* const* d_in, const int* in_sizes, int n_in,
                              void* d_out, int out_size)
{
    const float* x    = (const float*)d_in[0];
    const unsigned char* pad = (const unsigned char*)d_in[1];
    const float* Wqkv = (const float*)d_in[2];
    const float* bqkv = (const float*)d_in[3];
    const float* Wp   = (const float*)d_in[4];
    const float* bp   = (const float*)d_in[5];
    const float* scale = (const float*)d_in[6];
    float* out = (float*)d_out;

    float *qp, *kp, *vp;
    __nv_bfloat16 *xh, *xl, *wqh, *wql, *wph, *wpl, *ah, *al;
    cudaGetSymbolAddress((void**)&qp, g_q);
    cudaGetSymbolAddress((void**)&kp, g_k);
    cudaGetSymbolAddress((void**)&vp, g_v);
    cudaGetSymbolAddress((void**)&xh, g_xh);
    cudaGetSymbolAddress((void**)&xl, g_xl);
    cudaGetSymbolAddress((void**)&wqh, g_wqh);
    cudaGetSymbolAddress((void**)&wql, g_wql);
    cudaGetSymbolAddress((void**)&wph, g_wph);
    cudaGetSymbolAddress((void**)&wpl, g_wpl);
    cudaGetSymbolAddress((void**)&ah, g_ah);
    cudaGetSymbolAddress((void**)&al, g_al);

    cudaFuncSetAttribute(gemm_bf3<0>, cudaFuncAttributeMaxDynamicSharedMemorySize, GEMM_SMEM);
    cudaFuncSetAttribute(gemm_bf3<1>, cudaFuncAttributeMaxDynamicSharedMemorySize, GEMM_SMEM);
    cudaFuncSetAttribute(flash_attn, cudaFuncAttributeMaxDynamicSharedMemorySize, FA_SMEM);

    split_fp32<<<(8192*1024/4 + 255)/256, 256>>>(x, xh, xl, 8192*1024/4);
    split_fp32<<<(3072*1024/4 + 255)/256, 256>>>(Wqkv, wqh, wql, 3072*1024/4);
    split_fp32<<<(1024*1024/4 + 255)/256, 256>>>(Wp, wph, wpl, 1024*1024/4);

    dim3 g1(3072/128, 8192/128);
    gemm_bf3<0><<<g1, 256, GEMM_SMEM>>>(xh, xl, wqh, wql, bqkv, qp, kp, vp, 3072, 1024);

    dim3 g2(BATCH*NH, SEQ/64);
    flash_attn<<<g2, 256, FA_SMEM>>>(qp, kp, vp, pad, scale, ah, al);

    dim3 g3(1024/128, 8192/128);
    gemm_bf3<1><<<g3, 256, GEMM_SMEM>>>(ah, al, wph, wpl, bp, out, nullptr, nullptr, 1024, 1024);
}

// round 5
// speedup vs baseline: 3.0158x; 1.2636x over previous
#include <cuda_runtime.h>
#include <cuda_bf16.h>

#define FEAT 1024
#define NH   16
#define HD   64
#define BATCH 8
#define SEQ  1024

// ---------------- scratch (device globals; no allocation) ----------------
__device__ __nv_bfloat16 g_xh[8192*1024],  g_xl[8192*1024];
__device__ __nv_bfloat16 g_wqh[3072*1024], g_wql[3072*1024];
__device__ __nv_bfloat16 g_wph[1024*1024], g_wpl[1024*1024];
__device__ __nv_bfloat16 g_ah[8192*1024],  g_al[8192*1024];
__device__ __nv_bfloat16 g_qh[8192*1024],  g_ql[8192*1024];
__device__ __nv_bfloat16 g_kh[8192*1024],  g_kl[8192*1024];
__device__ __nv_bfloat16 g_vh[8192*1024],  g_vl[8192*1024];

// ---------------- helpers ----------------
__device__ __forceinline__ void ldsm4(unsigned r[4], unsigned addr) {
    asm volatile("ldmatrix.sync.aligned.m8n8.x4.shared.b16 {%0,%1,%2,%3}, [%4];\n"
                 : "=r"(r[0]), "=r"(r[1]), "=r"(r[2]), "=r"(r[3]) : "r"(addr));
}
__device__ __forceinline__ void mma_bf16(float c[4], const unsigned a[4], const unsigned b[2]) {
    asm volatile("mma.sync.aligned.m16n8k16.row.col.f32.bf16.bf16.f32 "
                 "{%0,%1,%2,%3}, {%4,%5,%6,%7}, {%8,%9}, {%0,%1,%2,%3};\n"
                 : "+f"(c[0]), "+f"(c[1]), "+f"(c[2]), "+f"(c[3])
                 : "r"(a[0]), "r"(a[1]), "r"(a[2]), "r"(a[3]), "r"(b[0]), "r"(b[1]));
}
__device__ __forceinline__ void cp16(unsigned dst, const void* src) {
    asm volatile("cp.async.cg.shared.global [%0], [%1], 16;\n" :: "r"(dst), "l"(src));
}
__device__ __forceinline__ unsigned pack_bf16x2(float lo, float hi) {
    unsigned r;
    asm("cvt.rn.bf16x2.f32 %0, %1, %2;\n" : "=r"(r) : "f"(hi), "f"(lo));
    return r;
}

// ---------------- fp32 -> bf16 hi/lo split ----------------
__global__ __launch_bounds__(256)
void split_fp32(const float* __restrict__ src, __nv_bfloat16* __restrict__ hi,
                __nv_bfloat16* __restrict__ lo, int n4)
{
    int i = blockIdx.x * blockDim.x + threadIdx.x;
    if (i >= n4) return;
    float4 v = ((const float4*)src)[i];
    __nv_bfloat16 h0 = __float2bfloat16(v.x);
    __nv_bfloat16 h1 = __float2bfloat16(v.y);
    __nv_bfloat16 h2 = __float2bfloat16(v.z);
    __nv_bfloat16 h3 = __float2bfloat16(v.w);
    ((unsigned*)hi)[2*i+0] = pack_bf16x2(v.x, 0.f) ? 0 : 0;  // placeholder avoided below
    __nv_bfloat162 hp0; hp0.x = h0; hp0.y = h1;
    __nv_bfloat162 hp1; hp1.x = h2; hp1.y = h3;
    ((__nv_bfloat162*)hi)[2*i+0] = hp0;
    ((__nv_bfloat162*)hi)[2*i+1] = hp1;
    __nv_bfloat162 lp0, lp1;
    lp0.x = __float2bfloat16(v.x - __bfloat162float(h0));
    lp0.y = __float2bfloat16(v.y - __bfloat162float(h1));
    lp1.x = __float2bfloat16(v.z - __bfloat162float(h2));
    lp1.y = __float2bfloat16(v.w - __bfloat162float(h3));
    ((__nv_bfloat162*)lo)[2*i+0] = lp0;
    ((__nv_bfloat162*)lo)[2*i+1] = lp1;
}

// ---------------- tensor-core GEMM: C = A @ W^T + bias (bf16x3) ----------------
#define AST 40
#define PLANE_B (128*AST*2)
#define BUF_B (4*PLANE_B)
#define GEMM_SMEM (2*BUF_B)

// EPILOGUE 0: scatter bf16 hi/lo to q/k/v planes ; EPILOGUE 1: fp32 row-major to outf
template<int EPILOGUE>
__global__ __launch_bounds__(256, 2)
void gemm_bf3(const __nv_bfloat16* __restrict__ Ah, const __nv_bfloat16* __restrict__ Al,
              const __nv_bfloat16* __restrict__ Wh, const __nv_bfloat16* __restrict__ Wl,
              const float* __restrict__ bias, float* __restrict__ outf,
              __nv_bfloat16* __restrict__ oqh, __nv_bfloat16* __restrict__ oql,
              __nv_bfloat16* __restrict__ okh, __nv_bfloat16* __restrict__ okl,
              __nv_bfloat16* __restrict__ ovh, __nv_bfloat16* __restrict__ ovl,
              int N, int K)
{
    extern __shared__ __nv_bfloat16 sm[];
    const int tid = threadIdx.x;
    const int bm = blockIdx.y * 128, bn = blockIdx.x * 128;
    const int w = tid >> 5, l = tid & 31;
    const int wm = w >> 2, wn = w & 3;

    const int lrow = tid >> 1, lcol = (tid & 1) * 16;
    const __nv_bfloat16* gA0 = Ah + (size_t)(bm + lrow) * K + lcol;
    const __nv_bfloat16* gA1 = Al + (size_t)(bm + lrow) * K + lcol;
    const __nv_bfloat16* gB0 = Wh + (size_t)(bn + lrow) * K + lcol;
    const __nv_bfloat16* gB1 = Wl + (size_t)(bn + lrow) * K + lcol;

    const unsigned sbase = (unsigned)__cvta_generic_to_shared(sm);
    const unsigned sst = sbase + lrow * (AST*2) + lcol * 2;

    float acc[4][4][4];
    #pragma unroll
    for (int i = 0; i < 4; i++)
        #pragma unroll
        for (int j = 0; j < 4; j++)
            #pragma unroll
            for (int r = 0; r < 4; r++) acc[i][j][r] = 0.f;

    auto issue = [&](int k0, int buf) {
        unsigned d = sst + buf * BUF_B;
        cp16(d,              gA0 + k0); cp16(d + 16,              gA0 + k0 + 8);
        cp16(d +   PLANE_B,  gA1 + k0); cp16(d +   PLANE_B + 16,  gA1 + k0 + 8);
        cp16(d + 2*PLANE_B,  gB0 + k0); cp16(d + 2*PLANE_B + 16,  gB0 + k0 + 8);
        cp16(d + 3*PLANE_B,  gB1 + k0); cp16(d + 3*PLANE_B + 16,  gB1 + k0 + 8);
        asm volatile("cp.async.commit_group;\n" ::: "memory");
    };

    issue(0, 0);
    int buf = 0;
    for (int k0 = 0; k0 < K; k0 += 32) {
        const bool more = (k0 + 32) < K;
        if (more) {
            issue(k0 + 32, buf ^ 1);
            asm volatile("cp.async.wait_group 1;\n" ::: "memory");
        } else {
            asm volatile("cp.async.wait_group 0;\n" ::: "memory");
        }
        __syncthreads();

        unsigned base = sbase + buf * BUF_B;
        #pragma unroll
        for (int g = 0; g < 2; g++) {
            unsigned ah[4][4], al[4][4], bh[4][2], bl[4][2];
            const int acol = g * 16 + (l >> 4) * 8;
            #pragma unroll
            for (int mt = 0; mt < 4; mt++) {
                int row = wm * 64 + mt * 16 + (l & 15);
                unsigned ad = base + row * (AST*2) + acol * 2;
                ldsm4(ah[mt], ad);
                ldsm4(al[mt], ad + PLANE_B);
            }
            {
                const int quad = l >> 3;
                const int nsub = quad >> 1, khalf = quad & 1;
                #pragma unroll
                for (int p = 0; p < 2; p++) {
                    int row = wn * 32 + (p*2 + nsub) * 8 + (l & 7);
                    int col = g * 16 + khalf * 8;
                    unsigned bd = base + 2*PLANE_B + row * (AST*2) + col * 2;
                    unsigned t[4];
                    ldsm4(t, bd);
                    bh[p*2][0] = t[0]; bh[p*2][1] = t[1];
                    bh[p*2+1][0] = t[2]; bh[p*2+1][1] = t[3];
                    ldsm4(t, bd + PLANE_B);
                    bl[p*2][0] = t[0]; bl[p*2][1] = t[1];
                    bl[p*2+1][0] = t[2]; bl[p*2+1][1] = t[3];
                }
            }
            #pragma unroll
            for (int mt = 0; mt < 4; mt++)
                #pragma unroll
                for (int nt = 0; nt < 4; nt++)
                    mma_bf16(acc[mt][nt], ah[mt], bh[nt]);
            #pragma unroll
            for (int mt = 0; mt < 4; mt++)
                #pragma unroll
                for (int nt = 0; nt < 4; nt++)
                    mma_bf16(acc[mt][nt], ah[mt], bl[nt]);
            #pragma unroll
            for (int mt = 0; mt < 4; mt++)
                #pragma unroll
                for (int nt = 0; nt < 4; nt++)
                    mma_bf16(acc[mt][nt], al[mt], bh[nt]);
        }
        __syncthreads();
        buf ^= 1;
    }

    const int gid = l >> 2, qid = l & 3;
    #pragma unroll
    for (int mt = 0; mt < 4; mt++) {
        #pragma unroll
        for (int nt = 0; nt < 4; nt++) {
            int n0 = bn + wn * 32 + nt * 8 + qid * 2;
            float bx = bias[n0], by = bias[n0 + 1];
            #pragma unroll
            for (int half = 0; half < 2; half++) {
                int m = bm + wm * 64 + mt * 16 + gid + half * 8;
                float cx = acc[mt][nt][half*2 + 0] + bx;
                float cy = acc[mt][nt][half*2 + 1] + by;
                if (EPILOGUE == 0) {
                    int b = m >> 10, t = m & 1023;
                    int s = n0 >> 10, r = n0 & 1023;
                    int hh = r >> 6, d = r & 63;
                    size_t off = ((size_t)(b*NH + hh)*SEQ + t) * HD + d;
                    __nv_bfloat16 hx = __float2bfloat16(cx);
                    __nv_bfloat16 hy = __float2bfloat16(cy);
                    float lx = cx - __bfloat162float(hx);
                    float ly = cy - __bfloat162float(hy);
                    __nv_bfloat16* dh = (s == 0 ? oqh : (s == 1 ? okh : ovh));
                    __nv_bfloat16* dl = (s == 0 ? oql : (s == 1 ? okl : ovl));
                    __nv_bfloat162 hp; hp.x = hx; hp.y = hy;
                    __nv_bfloat162 lp; lp.x = __float2bfloat16(lx); lp.y = __float2bfloat16(ly);
                    *(__nv_bfloat162*)(dh + off) = hp;
                    *(__nv_bfloat162*)(dl + off) = lp;
                } else {
                    float2 v2 = {cx, cy};
                    *(float2*)(outf + (size_t)m * N + n0) = v2;
                }
            }
        }
    }
}

// ---------------- tensor-core flash attention (bf16x3) ----------------
// CTA: 128 q rows of one (b,h); key tiles of 64. 8 warps, warp = 16 rows.
#define QST 72
#define KST 72
#define VST 72
#define SM_QH 0
#define SM_QL (128*QST)
#define SM_KH (2*128*QST)
#define SM_KL (2*128*QST + 64*KST)
#define SM_VH (2*128*QST + 2*64*KST)
#define SM_VL (2*128*QST + 2*64*KST + 64*VST)
#define SM_HALVES (2*128*QST + 2*64*KST + 2*64*VST)
#define ATTN_SMEM (SM_HALVES*2 + 1024)

__global__ __launch_bounds__(256)
void flash_attn_mma(const __nv_bfloat16* __restrict__ qh, const __nv_bfloat16* __restrict__ ql,
                    const __nv_bfloat16* __restrict__ kh, const __nv_bfloat16* __restrict__ kl,
                    const __nv_bfloat16* __restrict__ vh, const __nv_bfloat16* __restrict__ vl,
                    const unsigned char* __restrict__ pad, const float* __restrict__ scale_p,
                    __nv_bfloat16* __restrict__ outh, __nv_bfloat16* __restrict__ outl)
{
    extern __shared__ __nv_bfloat16 smh[];
    unsigned char* spad = (unsigned char*)(smh + SM_HALVES);
    const unsigned sbase = (unsigned)__cvta_generic_to_shared(smh);

    const int bh = blockIdx.x;
    const int b = bh >> 4, h = bh & 15;
    const int qb = (int)(gridDim.y - 1) - (int)blockIdx.y;   // heavy first
    const int q0 = qb * 128;
    const int tid = threadIdx.x;
    const int wid = tid >> 5, l = tid & 31;
    const int gid = l >> 2, qd = l & 3;
    const float scale = *scale_p;

    const int brow = ((l >> 4) & 1) * 8 + (l & 7);   // B-frag row-in-pair
    const int bcol = ((l >> 3) & 1) * 8;             // B-frag k-half

    // padding-mask row -> smem
    ((int*)spad)[tid] = ((const int*)(pad + (size_t)b*SEQ))[tid];

    // Q tiles hi/lo via cp.async (persistent)
    {
        const __nv_bfloat16* qsh = qh + ((size_t)bh*SEQ + q0)*HD;
        const __nv_bfloat16* qsl = ql + ((size_t)bh*SEQ + q0)*HD;
        #pragma unroll
        for (int it = 0; it < 4; it++) {
            int lin = it*256 + tid;
            int row = lin >> 3, seg = lin & 7;
            cp16(sbase + (SM_QH + row*QST)*2 + seg*16, qsh + (size_t)row*HD + seg*8);
            cp16(sbase + (SM_QL + row*QST)*2 + seg*16, qsl + (size_t)row*HD + seg*8);
        }
        asm volatile("cp.async.commit_group;\ncp.async.wait_group 0;\n" ::: "memory");
    }
    __syncthreads();

    // preload Q fragments (A operand), 4 k-steps x hi/lo
    unsigned qfh[4][4], qfl[4][4];
    {
        int row = wid*16 + (l & 15);
        int csel = (l >> 4) * 8;
        #pragma unroll
        for (int ks = 0; ks < 4; ks++) {
            unsigned ad = sbase + (SM_QH + row*QST + ks*16 + csel)*2;
            ldsm4(qfh[ks], ad);
            ad = sbase + (SM_QL + row*QST + ks*16 + csel)*2;
            ldsm4(qfl[ks], ad);
        }
    }

    float O[8][4];
    #pragma unroll
    for (int nt = 0; nt < 8; nt++)
        #pragma unroll
        for (int r = 0; r < 4; r++) O[nt][r] = 0.f;
    float mrow[2] = {-1e30f, -1e30f};
    float lrow[2] = {0.f, 0.f};

    const int r0g = q0 + wid*16 + gid;
    const int r1g = r0g + 8;
    const int nkt = 2*qb + 2;

    for (int kt = 0; kt < nkt; kt++) {
        const int kb = kt * 64;
        __syncthreads();   // previous tile's smem reads done

        // K tile hi/lo via cp.async
        {
            const __nv_bfloat16* ksh = kh + ((size_t)bh*SEQ + kb)*HD;
            const __nv_bfloat16* ksl = kl + ((size_t)bh*SEQ + kb)*HD;
            #pragma unroll
            for (int it = 0; it < 2; it++) {
                int lin = it*256 + tid;
                int row = lin >> 3, seg = lin & 7;
                cp16(sbase + (SM_KH + row*KST)*2 + seg*16, ksh + (size_t)row*HD + seg*8);
                cp16(sbase + (SM_KL + row*KST)*2 + seg*16, ksl + (size_t)row*HD + seg*8);
            }
            asm volatile("cp.async.commit_group;\n" ::: "memory");
        }
        // V tile, transposed store [d][key]
        {
            int t = tid >> 2;
            int db = (tid & 3) * 16;
            const __nv_bfloat16* vsh = vh + ((size_t)bh*SEQ + kb + t)*HD + db;
            const __nv_bfloat16* vsl = vl + ((size_t)bh*SEQ + kb + t)*HD + db;
            #pragma unroll
            for (int j = 0; j < 4; j++) {
                uint2 u = *(const uint2*)(vsh + j*4);
                __nv_bfloat162 a = *(__nv_bfloat162*)&u.x;
                __nv_bfloat162 c = *(__nv_bfloat162*)&u.y;
                smh[SM_VH + (db + j*4 + 0)*VST + t] = a.x;
                smh[SM_VH + (db + j*4 + 1)*VST + t] = a.y;
                smh[SM_VH + (db + j*4 + 2)*VST + t] = c.x;
                smh[SM_VH + (db + j*4 + 3)*VST + t] = c.y;
                u = *(const uint2*)(vsl + j*4);
                a = *(__nv_bfloat162*)&u.x;
                c = *(__nv_bfloat162*)&u.y;
                smh[SM_VL + (db + j*4 + 0)*VST + t] = a.x;
                smh[SM_VL + (db + j*4 + 1)*VST + t] = a.y;
                smh[SM_VL + (db + j*4 + 2)*VST + t] = c.x;
                smh[SM_VL + (db + j*4 + 3)*VST + t] = c.y;
            }
        }
        asm volatile("cp.async.wait_group 0;\n" ::: "memory");
        __syncthreads();

        // ---- S = Q K^T (3 planes) ----
        float sacc[8][4];
        #pragma unroll
        for (int nt = 0; nt < 8; nt++)
            #pragma unroll
            for (int r = 0; r < 4; r++) sacc[nt][r] = 0.f;

        #pragma unroll
        for (int ks = 0; ks < 4; ks++) {
            #pragma unroll
            for (int p = 0; p < 4; p++) {
                unsigned kh4[4], kl4[4];
                unsigned kd = sbase + (SM_KH + (p*16 + brow)*KST + ks*16 + bcol)*2;
                ldsm4(kh4, kd);
                kd = sbase + (SM_KL + (p*16 + brow)*KST + ks*16 + bcol)*2;
                ldsm4(kl4, kd);
                unsigned bh0[2] = {kh4[0], kh4[1]}, bh1[2] = {kh4[2], kh4[3]};
                unsigned bl0[2] = {kl4[0], kl4[1]}, bl1[2] = {kl4[2], kl4[3]};
                mma_bf16(sacc[2*p],   qfh[ks], bh0);
                mma_bf16(sacc[2*p+1], qfh[ks], bh1);
                mma_bf16(sacc[2*p],   qfh[ks], bl0);
                mma_bf16(sacc[2*p+1], qfh[ks], bl1);
                mma_bf16(sacc[2*p],   qfl[ks], bh0);
                mma_bf16(sacc[2*p+1], qfl[ks], bh1);
            }
        }

        // ---- scale + mask + online softmax ----
        float tmax0 = -1e30f, tmax1 = -1e30f;
        const bool do_causal = (kb + 63 > q0 + wid*16);
        #pragma unroll
        for (int nt = 0; nt < 8; nt++) {
            int c0 = kb + nt*8 + qd*2;
            bool pm0 = spad[c0] != 0, pm1 = spad[c0+1] != 0;
            float v00 = sacc[nt][0] * scale;
            float v01 = sacc[nt][1] * scale;
            float v10 = sacc[nt][2] * scale;
            float v11 = sacc[nt][3] * scale;
            if (pm0) { v00 = -1e30f; v10 = -1e30f; }
            if (pm1) { v01 = -1e30f; v11 = -1e30f; }
            if (do_causal) {
                if (c0   > r0g) v00 = -1e30f;
                if (c0+1 > r0g) v01 = -1e30f;
                if (c0   > r1g) v10 = -1e30f;
                if (c0+1 > r1g) v11 = -1e30f;
            }
            sacc[nt][0] = v00; sacc[nt][1] = v01;
            sacc[nt][2] = v10; sacc[nt][3] = v11;
            tmax0 = fmaxf(tmax0, fmaxf(v00, v01));
            tmax1 = fmaxf(tmax1, fmaxf(v10, v11));
        }
        tmax0 = fmaxf(tmax0, __shfl_xor_sync(0xffffffffu, tmax0, 1));
        tmax0 = fmaxf(tmax0, __shfl_xor_sync(0xffffffffu, tmax0, 2));
        tmax1 = fmaxf(tmax1, __shfl_xor_sync(0xffffffffu, tmax1, 1));
        tmax1 = fmaxf(tmax1, __shfl_xor_sync(0xffffffffu, tmax1, 2));

        float mn0 = fmaxf(mrow[0], tmax0);
        float mn1 = fmaxf(mrow[1], tmax1);
        float cf0 = __expf(mrow[0] - mn0);
        float cf1 = __expf(mrow[1] - mn1);
        mrow[0] = mn0; mrow[1] = mn1;

        float rs0 = 0.f, rs1 = 0.f;
        unsigned pfh[8][2], pfl[8][2];
        #pragma unroll
        for (int nt = 0; nt < 8; nt++) {
            float p00 = __expf(sacc[nt][0] - mn0);
            float p01 = __expf(sacc[nt][1] - mn0);
            float p10 = __expf(sacc[nt][2] - mn1);
            float p11 = __expf(sacc[nt][3] - mn1);
            rs0 += p00 + p01;
            rs1 += p10 + p11;
            float h00 = __bfloat162float(__float2bfloat16(p00));
            float h01 = __bfloat162float(__float2bfloat16(p01));
            float h10 = __bfloat162float(__float2bfloat16(p10));
            float h11 = __bfloat162float(__float2bfloat16(p11));
            pfh[nt][0] = pack_bf16x2(h00, h01);
            pfh[nt][1] = pack_bf16x2(h10, h11);
            pfl[nt][0] = pack_bf16x2(p00 - h00, p01 - h01);
            pfl[nt][1] = pack_bf16x2(p10 - h10, p11 - h11);
        }
        rs0 += __shfl_xor_sync(0xffffffffu, rs0, 1);
        rs0 += __shfl_xor_sync(0xffffffffu, rs0, 2);
        rs1 += __shfl_xor_sync(0xffffffffu, rs1, 1);
        rs1 += __shfl_xor_sync(0xffffffffu, rs1, 2);
        lrow[0] = lrow[0] * cf0 + rs0;
        lrow[1] = lrow[1] * cf1 + rs1;
        #pragma unroll
        for (int nt = 0; nt < 8; nt++) {
            O[nt][0] *= cf0; O[nt][1] *= cf0;
            O[nt][2] *= cf1; O[nt][3] *= cf1;
        }

        // ---- O += P V (3 planes) ----
        #pragma unroll
        for (int ks = 0; ks < 4; ks++) {
            unsigned pah[4] = {pfh[2*ks][0], pfh[2*ks][1], pfh[2*ks+1][0], pfh[2*ks+1][1]};
            unsigned pal[4] = {pfl[2*ks][0], pfl[2*ks][1], pfl[2*ks+1][0], pfl[2*ks+1][1]};
            #pragma unroll
            for (int p = 0; p < 4; p++) {
                unsigned vh4[4], vl4[4];
                unsigned vd = sbase + (SM_VH + (p*16 + brow)*VST + ks*16 + bcol)*2;
                ldsm4(vh4, vd);
                vd = sbase + (SM_VL + (p*16 + brow)*VST + ks*16 + bcol)*2;
                ldsm4(vl4, vd);
                unsigned bv0[2] = {vh4[0], vh4[1]}, bv1[2] = {vh4[2], vh4[3]};
                unsigned bw0[2] = {vl4[0], vl4[1]}, bw1[2] = {vl4[2], vl4[3]};
                mma_bf16(O[2*p],   pah, bv0);
                mma_bf16(O[2*p+1], pah, bv1);
                mma_bf16(O[2*p],   pah, bw0);
                mma_bf16(O[2*p+1], pah, bw1);
                mma_bf16(O[2*p],   pal, bv0);
                mma_bf16(O[2*p+1], pal, bv1);
            }
        }
    }

    // ---- epilogue: normalize, split, store ----
    float inv0 = 1.f / lrow[0];
    float inv1 = 1.f / lrow[1];
    #pragma unroll
    for (int nt = 0; nt < 8; nt++) {
        float o00 = O[nt][0] * inv0, o01 = O[nt][1] * inv0;
        float o10 = O[nt][2] * inv1, o11 = O[nt][3] * inv1;
        int col = h*HD + nt*8 + qd*2;
        size_t off0 = (size_t)(b*SEQ + r0g) * FEAT + col;
        size_t off1 = (size_t)(b*SEQ + r1g) * FEAT + col;
        float h00 = __bfloat162float(__float2bfloat16(o00));
        float h01 = __bfloat162float(__float2bfloat16(o01));
        float h10 = __bfloat162float(__float2bfloat16(o10));
        float h11 = __bfloat162float(__float2bfloat16(o11));
        *(unsigned*)(outh + off0) = pack_bf16x2(h00, h01);
        *(unsigned*)(outh + off1) = pack_bf16x2(h10, h11);
        *(unsigned*)(outl + off0) = pack_bf16x2(o00 - h00, o01 - h01);
        *(unsigned*)(outl + off1) = pack_bf16x2(o10 - h10, o11 - h11);
    }
}

// ---------------- launch ----------------
extern "C" void kernel_launch(void* const* d_in, const int* in_sizes, int n_in,
                              void* d_out, int out_size)
{
    const float* x    = (const float*)d_in[0];
    const unsigned char* pad = (const unsigned char*)d_in[1];
    const float* Wqkv = (const float*)d_in[2];
    const float* bqkv = (const float*)d_in[3];
    const float* Wp   = (const float*)d_in[4];
    const float* bp   = (const float*)d_in[5];
    const float* scale = (const float*)d_in[6];
    float* out = (float*)d_out;

    __nv_bfloat16 *xh, *xl, *wqh, *wql, *wph, *wpl, *ah, *al;
    __nv_bfloat16 *qhp, *qlp, *khp, *klp, *vhp, *vlp;
    cudaGetSymbolAddress((void**)&xh, g_xh);
    cudaGetSymbolAddress((void**)&xl, g_xl);
    cudaGetSymbolAddress((void**)&wqh, g_wqh);
    cudaGetSymbolAddress((void**)&wql, g_wql);
    cudaGetSymbolAddress((void**)&wph, g_wph);
    cudaGetSymbolAddress((void**)&wpl, g_wpl);
    cudaGetSymbolAddress((void**)&ah, g_ah);
    cudaGetSymbolAddress((void**)&al, g_al);
    cudaGetSymbolAddress((void**)&qhp, g_qh);
    cudaGetSymbolAddress((void**)&qlp, g_ql);
    cudaGetSymbolAddress((void**)&khp, g_kh);
    cudaGetSymbolAddress((void**)&klp, g_kl);
    cudaGetSymbolAddress((void**)&vhp, g_vh);
    cudaGetSymbolAddress((void**)&vlp, g_vl);

    cudaFuncSetAttribute(gemm_bf3<0>, cudaFuncAttributeMaxDynamicSharedMemorySize, GEMM_SMEM);
    cudaFuncSetAttribute(gemm_bf3<1>, cudaFuncAttributeMaxDynamicSharedMemorySize, GEMM_SMEM);
    cudaFuncSetAttribute(flash_attn_mma, cudaFuncAttributeMaxDynamicSharedMemorySize, ATTN_SMEM);

    split_fp32<<<(8192*1024/4 + 255)/256, 256>>>(x, xh, xl, 8192*1024/4);
    split_fp32<<<(3072*1024/4 + 255)/256, 256>>>(Wqkv, wqh, wql, 3072*1024/4);
    split_fp32<<<(1024*1024/4 + 255)/256, 256>>>(Wp, wph, wpl, 1024*1024/4);

    dim3 g1(3072/128, 8192/128);
    gemm_bf3<0><<<g1, 256, GEMM_SMEM>>>(xh, xl, wqh, wql, bqkv, nullptr,
                                        qhp, qlp, khp, klp, vhp, vlp, 3072, 1024);

    dim3 g2(BATCH*NH, SEQ/128);
    flash_attn_mma<<<g2, 256, ATTN_SMEM>>>(qhp, qlp, khp, klp, vhp, vlp,
                                           pad, scale, ah, al);

    dim3 g3(1024/128, 8192/128);
    gemm_bf3<1><<<g3, 256, GEMM_SMEM>>>(ah, al, wph, wpl, bp, out,
                                        nullptr, nullptr, nullptr, nullptr, nullptr, nullptr,
                                        1024, 1024);
}